// round 2
// baseline (speedup 1.0000x reference)
#include <cuda_runtime.h>
#include <math.h>

#define NN 50000
#define EE 800000
#define DH 128
#define DOUT 40

// ---------------- scratch (device globals; no allocation allowed) ----------------
__device__ float g_bufA[NN * DH];   // agg / h3
__device__ float g_bufB[NN * DH];   // t / logits
__device__ float g_bufC[NN * DH];   // h (conv output)
__device__ float g_sum[DH];
__device__ float g_sqsum[DH];
__device__ float g_scale[DH];
__device__ float g_shift[DH];

// ---------------- simple vector copy ----------------
__global__ void copy4_kernel(float4* __restrict__ dst, const float4* __restrict__ src, int n4) {
    int i = blockIdx.x * blockDim.x + threadIdx.x;
    if (i < n4) dst[i] = src[i];
}

// ---------------- scatter-add: one warp per edge, float4 vector reductions ----------------
// edge_index is int32 (JAX default x64-disabled truncates int64 -> int32).
__global__ void scatter_add_kernel(const float* __restrict__ X,
                                   const int* __restrict__ ei,
                                   float* __restrict__ agg, int nedges) {
    int gw = (blockIdx.x * blockDim.x + threadIdx.x) >> 5;
    int lane = threadIdx.x & 31;
    if (gw >= nedges) return;
    int src = __ldg(&ei[gw]);
    int dst = __ldg(&ei[nedges + gw]);
    // defensive clamp: wrong -> wrong answer (diagnosable), never illegal access
    src = min(max(src, 0), NN - 1);
    dst = min(max(dst, 0), NN - 1);
    float4 v = __ldg((const float4*)X + (size_t)src * 32 + lane);
    float* p = agg + (size_t)dst * DH + lane * 4;
    asm volatile("red.global.add.v4.f32 [%0], {%1, %2, %3, %4};"
                 :: "l"(p), "f"(v.x), "f"(v.y), "f"(v.z), "f"(v.w)
                 : "memory");
}

// ---------------- stats helpers ----------------
__global__ void zero_stats_kernel() {
    int c = threadIdx.x;
    if (c < DH) { g_sum[c] = 0.f; g_sqsum[c] = 0.f; }
}

__global__ void finalize_bn_kernel(const float* __restrict__ gamma,
                                   const float* __restrict__ beta, float invN) {
    int c = threadIdx.x;
    if (c < DH) {
        float mu  = g_sum[c] * invN;
        float var = g_sqsum[c] * invN - mu * mu;
        float rs  = rsqrtf(var + 1e-5f);
        float sc  = rs * __ldg(&gamma[c]);
        g_scale[c] = sc;
        g_shift[c] = __ldg(&beta[c]) - mu * sc;
    }
}

// apply BN (precomputed scale/shift) + ReLU in place, vectorized
__global__ void bn_relu_kernel(float4* __restrict__ T, int n4) {
    int i = blockIdx.x * blockDim.x + threadIdx.x;
    if (i >= n4) return;
    int c4 = i & 31;
    float4 v = T[i];
    float4 sc = ((const float4*)g_scale)[c4];
    float4 sh = ((const float4*)g_shift)[c4];
    v.x = fmaxf(v.x * sc.x + sh.x, 0.f);
    v.y = fmaxf(v.y * sc.y + sh.y, 0.f);
    v.z = fmaxf(v.z * sc.z + sh.z, 0.f);
    v.w = fmaxf(v.w * sc.w + sh.w, 0.f);
    T[i] = v;
}

// ---------------- main GEMM: Y[N,128] = X[N,128] @ W[128,128] + b ----------------
// 256 threads: cg = t&31 (4 cols), rg = t>>5 (4 rows). Tile = 32 rows/block.
// X loads are warp-broadcast float4 (L1), W loads coalesced float4 (L1, W=64KB resident).
template <bool RELU, bool STATS>
__global__ void __launch_bounds__(256) gemm128_kernel(
    const float* __restrict__ X, const float* __restrict__ W,
    const float* __restrict__ B, float* __restrict__ Y, int nrows)
{
    int t  = threadIdx.x;
    int cg = t & 31;
    int rg = t >> 5;
    int row0 = blockIdx.x * 32 + rg * 4;

    const float4* X4 = (const float4*)X;
    const float4* W4 = (const float4*)W;

    int  rowc[4];
    bool val[4];
#pragma unroll
    for (int r = 0; r < 4; r++) {
        int rr = row0 + r;
        val[r]  = rr < nrows;
        rowc[r] = val[r] ? rr : 0;
    }

    float acc[4][4];
#pragma unroll
    for (int r = 0; r < 4; r++)
#pragma unroll
        for (int j = 0; j < 4; j++) acc[r][j] = 0.f;

#pragma unroll 4
    for (int k = 0; k < 128; k += 4) {
        float4 w0 = W4[(k + 0) * 32 + cg];
        float4 w1 = W4[(k + 1) * 32 + cg];
        float4 w2 = W4[(k + 2) * 32 + cg];
        float4 w3 = W4[(k + 3) * 32 + cg];
#pragma unroll
        for (int r = 0; r < 4; r++) {
            float4 xv = X4[rowc[r] * 32 + (k >> 2)];
            acc[r][0] += xv.x * w0.x; acc[r][0] += xv.y * w1.x;
            acc[r][0] += xv.z * w2.x; acc[r][0] += xv.w * w3.x;
            acc[r][1] += xv.x * w0.y; acc[r][1] += xv.y * w1.y;
            acc[r][1] += xv.z * w2.y; acc[r][1] += xv.w * w3.y;
            acc[r][2] += xv.x * w0.z; acc[r][2] += xv.y * w1.z;
            acc[r][2] += xv.z * w2.z; acc[r][2] += xv.w * w3.z;
            acc[r][3] += xv.x * w0.w; acc[r][3] += xv.y * w1.w;
            acc[r][3] += xv.z * w2.w; acc[r][3] += xv.w * w3.w;
        }
    }

    float4 b4 = ((const float4*)B)[cg];
    float colsum[4] = {0.f, 0.f, 0.f, 0.f};
    float colsq[4]  = {0.f, 0.f, 0.f, 0.f};

#pragma unroll
    for (int r = 0; r < 4; r++) {
        if (!val[r]) continue;
        float y0 = acc[r][0] + b4.x;
        float y1 = acc[r][1] + b4.y;
        float y2 = acc[r][2] + b4.z;
        float y3 = acc[r][3] + b4.w;
        if (RELU) {
            y0 = fmaxf(y0, 0.f); y1 = fmaxf(y1, 0.f);
            y2 = fmaxf(y2, 0.f); y3 = fmaxf(y3, 0.f);
        }
        if (STATS) {
            colsum[0] += y0; colsq[0] += y0 * y0;
            colsum[1] += y1; colsq[1] += y1 * y1;
            colsum[2] += y2; colsq[2] += y2 * y2;
            colsum[3] += y3; colsq[3] += y3 * y3;
        }
        float4 o; o.x = y0; o.y = y1; o.z = y2; o.w = y3;
        ((float4*)Y)[rowc[r] * 32 + cg] = o;
    }

    if (STATS) {
        __shared__ float ssum[8][128];
        __shared__ float ssq[8][128];
#pragma unroll
        for (int j = 0; j < 4; j++) {
            ssum[rg][cg * 4 + j] = colsum[j];
            ssq[rg][cg * 4 + j]  = colsq[j];
        }
        __syncthreads();
        if (t < 128) {
            float s = 0.f;
#pragma unroll
            for (int g = 0; g < 8; g++) s += ssum[g][t];
            atomicAdd(&g_sum[t], s);
        } else {
            int c = t - 128;
            float s = 0.f;
#pragma unroll
            for (int g = 0; g < 8; g++) s += ssq[g][c];
            atomicAdd(&g_sqsum[c], s);
        }
    }
}

// ---------------- head GEMM: logits[N,40] = X[N,128] @ W[128,40] + b ----------------
// 320 threads: cg = t%10 (4 cols), rg = t/10 (4 rows). Tile = 128 rows/block.
__global__ void __launch_bounds__(320) gemm40_kernel(
    const float* __restrict__ X, const float* __restrict__ W,
    const float* __restrict__ B, float* __restrict__ Y, int nrows)
{
    int t  = threadIdx.x;
    int rg = t / 10;
    int cg = t - rg * 10;
    int row0 = blockIdx.x * 128 + rg * 4;

    const float4* X4 = (const float4*)X;
    const float4* W4 = (const float4*)W;

    int  rowc[4];
    bool val[4];
#pragma unroll
    for (int r = 0; r < 4; r++) {
        int rr = row0 + r;
        val[r]  = rr < nrows;
        rowc[r] = val[r] ? rr : 0;
    }

    float acc[4][4];
#pragma unroll
    for (int r = 0; r < 4; r++)
#pragma unroll
        for (int j = 0; j < 4; j++) acc[r][j] = 0.f;

#pragma unroll 4
    for (int k = 0; k < 128; k += 4) {
        float4 w0 = W4[(k + 0) * 10 + cg];
        float4 w1 = W4[(k + 1) * 10 + cg];
        float4 w2 = W4[(k + 2) * 10 + cg];
        float4 w3 = W4[(k + 3) * 10 + cg];
#pragma unroll
        for (int r = 0; r < 4; r++) {
            float4 xv = X4[rowc[r] * 32 + (k >> 2)];
            acc[r][0] += xv.x * w0.x; acc[r][0] += xv.y * w1.x;
            acc[r][0] += xv.z * w2.x; acc[r][0] += xv.w * w3.x;
            acc[r][1] += xv.x * w0.y; acc[r][1] += xv.y * w1.y;
            acc[r][1] += xv.z * w2.y; acc[r][1] += xv.w * w3.y;
            acc[r][2] += xv.x * w0.z; acc[r][2] += xv.y * w1.z;
            acc[r][2] += xv.z * w2.z; acc[r][2] += xv.w * w3.z;
            acc[r][3] += xv.x * w0.w; acc[r][3] += xv.y * w1.w;
            acc[r][3] += xv.z * w2.w; acc[r][3] += xv.w * w3.w;
        }
    }

    float4 b4 = ((const float4*)B)[cg];
#pragma unroll
    for (int r = 0; r < 4; r++) {
        if (!val[r]) continue;
        float4 o;
        o.x = acc[r][0] + b4.x;
        o.y = acc[r][1] + b4.y;
        o.z = acc[r][2] + b4.z;
        o.w = acc[r][3] + b4.w;
        ((float4*)Y)[rowc[r] * 10 + cg] = o;
    }
}

// ---------------- log-softmax over 40 columns, one row per thread ----------------
__global__ void logsoftmax40_kernel(const float* __restrict__ L, float* __restrict__ out, int nrows) {
    int row = blockIdx.x * blockDim.x + threadIdx.x;
    if (row >= nrows) return;
    const float4* l4 = (const float4*)(L + (size_t)row * DOUT);
    float v[DOUT];
#pragma unroll
    for (int i = 0; i < 10; i++) {
        float4 a = __ldg(&l4[i]);
        v[i * 4 + 0] = a.x; v[i * 4 + 1] = a.y; v[i * 4 + 2] = a.z; v[i * 4 + 3] = a.w;
    }
    float m = v[0];
#pragma unroll
    for (int j = 1; j < DOUT; j++) m = fmaxf(m, v[j]);
    float s = 0.f;
#pragma unroll
    for (int j = 0; j < DOUT; j++) s += expf(v[j] - m);
    float lse = logf(s) + m;
    float4* o4 = (float4*)(out + (size_t)row * DOUT);
#pragma unroll
    for (int i = 0; i < 10; i++) {
        float4 o;
        o.x = v[i * 4 + 0] - lse; o.y = v[i * 4 + 1] - lse;
        o.z = v[i * 4 + 2] - lse; o.w = v[i * 4 + 3] - lse;
        o4[i] = o;
    }
}

// ---------------- host launch ----------------
extern "C" void kernel_launch(void* const* d_in, const int* in_sizes, int n_in,
                              void* d_out, int out_size) {
    const float* x   = (const float*)d_in[0];
    const int*   ei  = (const int*)d_in[1];   // int32 (JAX x64 disabled)
    const float* W1a = (const float*)d_in[2];
    const float* b1a = (const float*)d_in[3];
    const float* g1  = (const float*)d_in[4];
    const float* be1 = (const float*)d_in[5];
    const float* W2a = (const float*)d_in[6];
    const float* b2a = (const float*)d_in[7];
    const float* W1b = (const float*)d_in[8];
    const float* b1b = (const float*)d_in[9];
    const float* g2  = (const float*)d_in[10];
    const float* be2 = (const float*)d_in[11];
    const float* W2b = (const float*)d_in[12];
    const float* b2b = (const float*)d_in[13];
    const float* Wl1 = (const float*)d_in[14];
    const float* bl1 = (const float*)d_in[15];
    const float* Wl2 = (const float*)d_in[16];
    const float* bl2 = (const float*)d_in[17];
    float* out = (float*)d_out;

    float *pA, *pB, *pC;
    cudaGetSymbolAddress((void**)&pA, g_bufA);
    cudaGetSymbolAddress((void**)&pB, g_bufB);
    cudaGetSymbolAddress((void**)&pC, g_bufC);

    const int n4      = NN * 32;                 // float4 count of an N x 128 buffer
    const int copyGrid = (n4 + 255) / 256;
    const int scatGrid = (EE + 7) / 8;           // 8 warps (edges) per 256-thread block
    const int gemmGrid = (NN + 31) / 32;
    const float invN = 1.0f / (float)NN;

    // ---- conv1 ----
    copy4_kernel<<<copyGrid, 256>>>((float4*)pA, (const float4*)x, n4);
    scatter_add_kernel<<<scatGrid, 256>>>(x, ei, pA, EE);
    zero_stats_kernel<<<1, 128>>>();
    gemm128_kernel<false, true><<<gemmGrid, 256>>>(pA, W1a, b1a, pB, NN);
    finalize_bn_kernel<<<1, 128>>>(g1, be1, invN);
    bn_relu_kernel<<<copyGrid, 256>>>((float4*)pB, n4);
    gemm128_kernel<true, false><<<gemmGrid, 256>>>(pB, W2a, b2a, pC, NN);
    // (outer ReLU after conv1 is a no-op on already-ReLU'd output)

    // ---- conv2 ----
    copy4_kernel<<<copyGrid, 256>>>((float4*)pA, (const float4*)pC, n4);
    scatter_add_kernel<<<scatGrid, 256>>>(pC, ei, pA, EE);
    zero_stats_kernel<<<1, 128>>>();
    gemm128_kernel<false, true><<<gemmGrid, 256>>>(pA, W1b, b1b, pB, NN);
    finalize_bn_kernel<<<1, 128>>>(g2, be2, invN);
    bn_relu_kernel<<<copyGrid, 256>>>((float4*)pB, n4);
    gemm128_kernel<true, false><<<gemmGrid, 256>>>(pB, W2b, b2b, pC, NN);

    // ---- head ----
    gemm128_kernel<true, false><<<gemmGrid, 256>>>(pC, Wl1, bl1, pA, NN);
    gemm40_kernel<<<(NN + 127) / 128, 320>>>(pA, Wl2, bl2, pB, NN);
    logsoftmax40_kernel<<<(NN + 255) / 256, 256>>>(pB, out, NN);
}

// round 3
// speedup vs baseline: 1.1713x; 1.1713x over previous
#include <cuda_runtime.h>
#include <math.h>

#define NN 50000
#define EE 800000
#define DH 128
#define DOUT 40

// ---------------- scratch (device globals; no allocation allowed) ----------------
__device__ float g_bufA[NN * DH];   // agg / h3
__device__ float g_bufB[NN * DH];   // t / logits
__device__ float g_bufC[NN * DH];   // h (conv output)
__device__ float g_sum[DH];
__device__ float g_sqsum[DH];
__device__ float g_scale[DH];
__device__ float g_shift[DH];

// ---------------- simple vector copy ----------------
__global__ void copy4_kernel(float4* __restrict__ dst, const float4* __restrict__ src, int n4) {
    int i = blockIdx.x * blockDim.x + threadIdx.x;
    if (i < n4) dst[i] = src[i];
}

// ---------------- scatter-add: one warp per edge, float4 vector reductions ----------------
__global__ void scatter_add_kernel(const float* __restrict__ X,
                                   const int* __restrict__ ei,
                                   float* __restrict__ agg, int nedges) {
    int gw = (blockIdx.x * blockDim.x + threadIdx.x) >> 5;
    int lane = threadIdx.x & 31;
    if (gw >= nedges) return;
    int src = __ldg(&ei[gw]);
    int dst = __ldg(&ei[nedges + gw]);
    src = min(max(src, 0), NN - 1);
    dst = min(max(dst, 0), NN - 1);
    float4 v = __ldg((const float4*)X + (size_t)src * 32 + lane);
    float* p = agg + (size_t)dst * DH + lane * 4;
    asm volatile("red.global.add.v4.f32 [%0], {%1, %2, %3, %4};"
                 :: "l"(p), "f"(v.x), "f"(v.y), "f"(v.z), "f"(v.w)
                 : "memory");
}

// ---------------- stats helpers ----------------
__global__ void zero_stats_kernel() {
    int c = threadIdx.x;
    if (c < DH) { g_sum[c] = 0.f; g_sqsum[c] = 0.f; }
}

__global__ void finalize_bn_kernel(const float* __restrict__ gamma,
                                   const float* __restrict__ beta, float invN) {
    int c = threadIdx.x;
    if (c < DH) {
        float mu  = g_sum[c] * invN;
        float var = g_sqsum[c] * invN - mu * mu;
        float rs  = rsqrtf(var + 1e-5f);
        float sc  = rs * __ldg(&gamma[c]);
        g_scale[c] = sc;
        g_shift[c] = __ldg(&beta[c]) - mu * sc;
    }
}

// apply BN (precomputed scale/shift) + ReLU in place, vectorized
__global__ void bn_relu_kernel(float4* __restrict__ T, int n4) {
    int i = blockIdx.x * blockDim.x + threadIdx.x;
    if (i >= n4) return;
    int c4 = i & 31;
    float4 v = T[i];
    float4 sc = ((const float4*)g_scale)[c4];
    float4 sh = ((const float4*)g_shift)[c4];
    v.x = fmaxf(v.x * sc.x + sh.x, 0.f);
    v.y = fmaxf(v.y * sc.y + sh.y, 0.f);
    v.z = fmaxf(v.z * sc.z + sh.z, 0.f);
    v.w = fmaxf(v.w * sc.w + sh.w, 0.f);
    T[i] = v;
}

// ---------------- main GEMM: Y[N,128] = X[N,128] @ W[128,128] + b ----------------
// 256 threads, 64 rows/block. Each warp owns 8 rows; each thread owns 8 rows x 4 cols.
// Per 4-k inner iter: 128 FFMA vs 12 LDG -> ~91% of issue slots are FFMA.
template <bool RELU, bool STATS>
__global__ void __launch_bounds__(256, 2) gemm128_kernel(
    const float* __restrict__ X, const float* __restrict__ W,
    const float* __restrict__ B, float* __restrict__ Y, int nrows)
{
    int t   = threadIdx.x;
    int cg  = t & 31;       // column group: cols [cg*4, cg*4+4)
    int wid = t >> 5;       // 8 warps, 8 rows each
    int row0 = blockIdx.x * 64 + wid * 8;

    const float4* X4 = (const float4*)X;
    const float4* W4 = (const float4*)W;

    int  rowc[8];
    bool val[8];
#pragma unroll
    for (int r = 0; r < 8; r++) {
        int rr = row0 + r;
        val[r]  = rr < nrows;
        rowc[r] = (val[r] ? rr : 0) * 32;
    }

    float acc[8][4];
#pragma unroll
    for (int r = 0; r < 8; r++)
#pragma unroll
        for (int j = 0; j < 4; j++) acc[r][j] = 0.f;

#pragma unroll 2
    for (int k = 0; k < 128; k += 4) {
        float4 w0 = W4[(k + 0) * 32 + cg];
        float4 w1 = W4[(k + 1) * 32 + cg];
        float4 w2 = W4[(k + 2) * 32 + cg];
        float4 w3 = W4[(k + 3) * 32 + cg];
#pragma unroll
        for (int r = 0; r < 8; r++) {
            float4 xv = X4[rowc[r] + (k >> 2)];
            acc[r][0] += xv.x * w0.x; acc[r][0] += xv.y * w1.x;
            acc[r][0] += xv.z * w2.x; acc[r][0] += xv.w * w3.x;
            acc[r][1] += xv.x * w0.y; acc[r][1] += xv.y * w1.y;
            acc[r][1] += xv.z * w2.y; acc[r][1] += xv.w * w3.y;
            acc[r][2] += xv.x * w0.z; acc[r][2] += xv.y * w1.z;
            acc[r][2] += xv.z * w2.z; acc[r][2] += xv.w * w3.z;
            acc[r][3] += xv.x * w0.w; acc[r][3] += xv.y * w1.w;
            acc[r][3] += xv.z * w2.w; acc[r][3] += xv.w * w3.w;
        }
    }

    float4 b4 = ((const float4*)B)[cg];
    float colsum[4] = {0.f, 0.f, 0.f, 0.f};
    float colsq[4]  = {0.f, 0.f, 0.f, 0.f};

#pragma unroll
    for (int r = 0; r < 8; r++) {
        if (!val[r]) continue;
        float y0 = acc[r][0] + b4.x;
        float y1 = acc[r][1] + b4.y;
        float y2 = acc[r][2] + b4.z;
        float y3 = acc[r][3] + b4.w;
        if (RELU) {
            y0 = fmaxf(y0, 0.f); y1 = fmaxf(y1, 0.f);
            y2 = fmaxf(y2, 0.f); y3 = fmaxf(y3, 0.f);
        }
        if (STATS) {
            colsum[0] += y0; colsq[0] += y0 * y0;
            colsum[1] += y1; colsq[1] += y1 * y1;
            colsum[2] += y2; colsq[2] += y2 * y2;
            colsum[3] += y3; colsq[3] += y3 * y3;
        }
        float4 o; o.x = y0; o.y = y1; o.z = y2; o.w = y3;
        ((float4*)Y)[rowc[r] + cg] = o;
    }

    if (STATS) {
        __shared__ float ssum[8][128];
        __shared__ float ssq[8][128];
#pragma unroll
        for (int j = 0; j < 4; j++) {
            ssum[wid][cg * 4 + j] = colsum[j];
            ssq[wid][cg * 4 + j]  = colsq[j];
        }
        __syncthreads();
        if (t < 128) {
            float s = 0.f;
#pragma unroll
            for (int g = 0; g < 8; g++) s += ssum[g][t];
            atomicAdd(&g_sum[t], s);
        } else {
            int c = t - 128;
            float s = 0.f;
#pragma unroll
            for (int g = 0; g < 8; g++) s += ssq[g][c];
            atomicAdd(&g_sqsum[c], s);
        }
    }
}

// ---------------- head GEMM: logits[N,40] = X[N,128] @ W[128,40] + b ----------------
__global__ void __launch_bounds__(320) gemm40_kernel(
    const float* __restrict__ X, const float* __restrict__ W,
    const float* __restrict__ B, float* __restrict__ Y, int nrows)
{
    int t  = threadIdx.x;
    int rg = t / 10;
    int cg = t - rg * 10;
    int row0 = blockIdx.x * 128 + rg * 4;

    const float4* X4 = (const float4*)X;
    const float4* W4 = (const float4*)W;

    int  rowc[4];
    bool val[4];
#pragma unroll
    for (int r = 0; r < 4; r++) {
        int rr = row0 + r;
        val[r]  = rr < nrows;
        rowc[r] = val[r] ? rr : 0;
    }

    float acc[4][4];
#pragma unroll
    for (int r = 0; r < 4; r++)
#pragma unroll
        for (int j = 0; j < 4; j++) acc[r][j] = 0.f;

#pragma unroll 4
    for (int k = 0; k < 128; k += 4) {
        float4 w0 = W4[(k + 0) * 10 + cg];
        float4 w1 = W4[(k + 1) * 10 + cg];
        float4 w2 = W4[(k + 2) * 10 + cg];
        float4 w3 = W4[(k + 3) * 10 + cg];
#pragma unroll
        for (int r = 0; r < 4; r++) {
            float4 xv = X4[rowc[r] * 32 + (k >> 2)];
            acc[r][0] += xv.x * w0.x; acc[r][0] += xv.y * w1.x;
            acc[r][0] += xv.z * w2.x; acc[r][0] += xv.w * w3.x;
            acc[r][1] += xv.x * w0.y; acc[r][1] += xv.y * w1.y;
            acc[r][1] += xv.z * w2.y; acc[r][1] += xv.w * w3.y;
            acc[r][2] += xv.x * w0.z; acc[r][2] += xv.y * w1.z;
            acc[r][2] += xv.z * w2.z; acc[r][2] += xv.w * w3.z;
            acc[r][3] += xv.x * w0.w; acc[r][3] += xv.y * w1.w;
            acc[r][3] += xv.z * w2.w; acc[r][3] += xv.w * w3.w;
        }
    }

    float4 b4 = ((const float4*)B)[cg];
#pragma unroll
    for (int r = 0; r < 4; r++) {
        if (!val[r]) continue;
        float4 o;
        o.x = acc[r][0] + b4.x;
        o.y = acc[r][1] + b4.y;
        o.z = acc[r][2] + b4.z;
        o.w = acc[r][3] + b4.w;
        ((float4*)Y)[rowc[r] * 10 + cg] = o;
    }
}

// ---------------- log-softmax over 40 columns, one row per thread ----------------
__global__ void logsoftmax40_kernel(const float* __restrict__ L, float* __restrict__ out, int nrows) {
    int row = blockIdx.x * blockDim.x + threadIdx.x;
    if (row >= nrows) return;
    const float4* l4 = (const float4*)(L + (size_t)row * DOUT);
    float v[DOUT];
#pragma unroll
    for (int i = 0; i < 10; i++) {
        float4 a = __ldg(&l4[i]);
        v[i * 4 + 0] = a.x; v[i * 4 + 1] = a.y; v[i * 4 + 2] = a.z; v[i * 4 + 3] = a.w;
    }
    float m = v[0];
#pragma unroll
    for (int j = 1; j < DOUT; j++) m = fmaxf(m, v[j]);
    float s = 0.f;
#pragma unroll
    for (int j = 0; j < DOUT; j++) s += expf(v[j] - m);
    float lse = logf(s) + m;
    float4* o4 = (float4*)(out + (size_t)row * DOUT);
#pragma unroll
    for (int i = 0; i < 10; i++) {
        float4 o;
        o.x = v[i * 4 + 0] - lse; o.y = v[i * 4 + 1] - lse;
        o.z = v[i * 4 + 2] - lse; o.w = v[i * 4 + 3] - lse;
        o4[i] = o;
    }
}

// ---------------- host launch ----------------
extern "C" void kernel_launch(void* const* d_in, const int* in_sizes, int n_in,
                              void* d_out, int out_size) {
    const float* x   = (const float*)d_in[0];
    const int*   ei  = (const int*)d_in[1];   // int32 (JAX x64 disabled)
    const float* W1a = (const float*)d_in[2];
    const float* b1a = (const float*)d_in[3];
    const float* g1  = (const float*)d_in[4];
    const float* be1 = (const float*)d_in[5];
    const float* W2a = (const float*)d_in[6];
    const float* b2a = (const float*)d_in[7];
    const float* W1b = (const float*)d_in[8];
    const float* b1b = (const float*)d_in[9];
    const float* g2  = (const float*)d_in[10];
    const float* be2 = (const float*)d_in[11];
    const float* W2b = (const float*)d_in[12];
    const float* b2b = (const float*)d_in[13];
    const float* Wl1 = (const float*)d_in[14];
    const float* bl1 = (const float*)d_in[15];
    const float* Wl2 = (const float*)d_in[16];
    const float* bl2 = (const float*)d_in[17];
    float* out = (float*)d_out;

    float *pA, *pB, *pC;
    cudaGetSymbolAddress((void**)&pA, g_bufA);
    cudaGetSymbolAddress((void**)&pB, g_bufB);
    cudaGetSymbolAddress((void**)&pC, g_bufC);

    const int n4       = NN * 32;
    const int copyGrid = (n4 + 255) / 256;
    const int scatGrid = (EE + 7) / 8;
    const int gemmGrid = (NN + 63) / 64;
    const float invN = 1.0f / (float)NN;

    // ---- conv1 ----
    copy4_kernel<<<copyGrid, 256>>>((float4*)pA, (const float4*)x, n4);
    scatter_add_kernel<<<scatGrid, 256>>>(x, ei, pA, EE);
    zero_stats_kernel<<<1, 128>>>();
    gemm128_kernel<false, true><<<gemmGrid, 256>>>(pA, W1a, b1a, pB, NN);
    finalize_bn_kernel<<<1, 128>>>(g1, be1, invN);
    bn_relu_kernel<<<copyGrid, 256>>>((float4*)pB, n4);
    gemm128_kernel<true, false><<<gemmGrid, 256>>>(pB, W2a, b2a, pC, NN);

    // ---- conv2 ----
    copy4_kernel<<<copyGrid, 256>>>((float4*)pA, (const float4*)pC, n4);
    scatter_add_kernel<<<scatGrid, 256>>>(pC, ei, pA, EE);
    zero_stats_kernel<<<1, 128>>>();
    gemm128_kernel<false, true><<<gemmGrid, 256>>>(pA, W1b, b1b, pB, NN);
    finalize_bn_kernel<<<1, 128>>>(g2, be2, invN);
    bn_relu_kernel<<<copyGrid, 256>>>((float4*)pB, n4);
    gemm128_kernel<true, false><<<gemmGrid, 256>>>(pB, W2b, b2b, pC, NN);

    // ---- head ----
    gemm128_kernel<true, false><<<gemmGrid, 256>>>(pC, Wl1, bl1, pA, NN);
    gemm40_kernel<<<(NN + 127) / 128, 320>>>(pA, Wl2, bl2, pB, NN);
    logsoftmax40_kernel<<<(NN + 255) / 256, 256>>>(pB, out, NN);
}